// round 7
// baseline (speedup 1.0000x reference)
#include <cuda_runtime.h>

#define GH 64
#define GW 64
#define NOBJ 16
#define FEAT 256
#define BATCH 4
#define DECAY 0.95f

#define NROWS (BATCH * GH * GW * NOBJ)   // 262144
#define ROW_OUT (FEAT + 2)               // 258 floats = 1032 B
#define RPB NOBJ                         // one cell (16 object-rows) per block
#define TILE_F (RPB * ROW_OUT)           // 4128 floats = 16512 B

// One block per grid cell (b,gh,gw).
// Stage the full 16-row output chunk (16512 B) in smem in exact output layout,
// then stream it to gmem as 1032 perfectly aligned, fully dense STG.128 —
// eliminating the partial-sector writes caused by the odd 1032 B row pitch.
__global__ __launch_bounds__(256, 8)
void smg_kernel(const float* __restrict__ grid_state,
                const float* __restrict__ grid_conf,
                const float* __restrict__ grid_temp,
                const float* __restrict__ obj_feat,
                const float* __restrict__ positions,
                const float* __restrict__ occl,
                float* __restrict__ out)
{
    __shared__ __align__(16) float s[TILE_F];
    __shared__ float s_alpha[NOBJ];

    const int tid  = threadIdx.x;
    const int cell = blockIdx.x;                 // 0 .. 16383
    const int gw   = cell & (GW - 1);
    const int gh   = (cell >> 6) & (GH - 1);
    const int b    = cell >> 12;
    const int row0 = cell * RPB;

    // ---- Bulk loads first: 4x LDG.128 per thread, front-batched ----
    const float4* gs = (const float4*)grid_state + (size_t)row0 * (FEAT / 4);
    float4 v[4];
    #pragma unroll
    for (int j = 0; j < 4; j++)
        v[j] = gs[tid + 256 * j];

    // ---- Phase 0: per-object scalars (threads 0..15) ----
    if (tid < NOBJ) {
        const int o   = tid;
        const int bo  = b * NOBJ + o;
        const int row = row0 + o;
        const float px = positions[bo * 2 + 0];
        const float py = positions[bo * 2 + 1];
        const int gwt = (int)fminf(fmaxf(px * (float)(GW - 1), 0.0f), 63.0f);
        const int ght = (int)fminf(fmaxf(py * (float)(GH - 1), 0.0f), 63.0f);
        const bool upd = (gwt == gw) && (ght == gh);
        const bool vis = occl[bo] < 0.5f;

        s_alpha[o] = upd ? (vis ? 0.8f : 0.3f) : 0.0f;

        float c  = grid_conf[row];
        float tm = grid_temp[row];
        if (upd) {
            c  = vis ? fminf(1.0f, c * 0.9f + 0.5f) : c * DECAY;
            tm += vis ? 1.0f : 0.5f;
        }
        s[o * ROW_OUT + FEAT]     = c * DECAY;
        s[o * ROW_OUT + FEAT + 1] = tm;
    }
    __syncthreads();

    // ---- Phase 1: blend + stage features (float2 STS; rows may be 8-mod-16) ----
    #pragma unroll
    for (int j = 0; j < 4; j++) {
        const int idx = tid + 256 * j;           // 0..1023
        const int rl  = idx >> 6;                // local row (object), warp-uniform
        const int q   = idx & 63;                // float4 index within row
        const float a = s_alpha[rl];
        if (a != 0.0f) {                         // warp-uniform, ~never taken
            const int bo = b * NOBJ + rl;
            const float4 o4 = ((const float4*)(obj_feat + (size_t)bo * FEAT))[q];
            const float ia = 1.0f - a;
            v[j].x = a * o4.x + ia * v[j].x;
            v[j].y = a * o4.y + ia * v[j].y;
            v[j].z = a * o4.z + ia * v[j].z;
            v[j].w = a * o4.w + ia * v[j].w;
        }
        float* sp = s + rl * ROW_OUT + 4 * q;    // even float offset -> 8B aligned
        *(float2*)(sp)     = make_float2(v[j].x, v[j].y);
        *(float2*)(sp + 2) = make_float2(v[j].z, v[j].w);
    }
    __syncthreads();

    // ---- Phase 2: tile -> gmem, 1032 aligned dense STG.128 ----
    float4*       op = (float4*)(out + (size_t)row0 * ROW_OUT); // 16512B-multiple base
    const float4* spv = (const float4*)s;
    #pragma unroll
    for (int j = 0; j < 4; j++)
        op[tid + 256 * j] = spv[tid + 256 * j];
    if (tid < 8)
        op[1024 + tid] = spv[1024 + tid];
}

extern "C" void kernel_launch(void* const* d_in, const int* in_sizes, int n_in,
                              void* d_out, int out_size)
{
    const float* grid_state = (const float*)d_in[0];
    const float* grid_conf  = (const float*)d_in[1];
    const float* grid_temp  = (const float*)d_in[2];
    const float* obj_feat   = (const float*)d_in[3];
    const float* positions  = (const float*)d_in[4];
    const float* occl       = (const float*)d_in[5];
    float* out = (float*)d_out;

    smg_kernel<<<NROWS / RPB, 256>>>(grid_state, grid_conf, grid_temp,
                                     obj_feat, positions, occl, out);
}

// round 8
// speedup vs baseline: 1.0998x; 1.0998x over previous
#include <cuda_runtime.h>

#define GH 64
#define GW 64
#define NOBJ 16
#define FEAT 256
#define BATCH 4
#define DECAY 0.95f

#define NROWS (BATCH * GH * GW * NOBJ)   // 262144
#define ROW_OUT (FEAT + 2)               // 258 floats = 1032 B

// Fully warp-autonomous: no smem, no __syncthreads.
// Each warp owns 2 consecutive rows (one object pair within one cell).
// Lanes 0/1 compute the per-row update scalars and write the trailing
// (conf*DECAY, temporal) float2; shfl broadcasts the blend alphas.
// Feature mapping: float4 index = lane + 32*j -> j=0,1 cover row0,
// j=2,3 cover row1, every wavefront fully coalesced.
__global__ __launch_bounds__(256, 8)
void smg_kernel(const float* __restrict__ grid_state,
                const float* __restrict__ grid_conf,
                const float* __restrict__ grid_temp,
                const float* __restrict__ obj_feat,
                const float* __restrict__ positions,
                const float* __restrict__ occl,
                float* __restrict__ out)
{
    const int tid   = threadIdx.x;
    const int lane  = tid & 31;
    const int wglob = blockIdx.x * 8 + (tid >> 5);  // global warp id
    const int r0    = wglob * 2;                    // first of this warp's 2 rows
    const int cell  = r0 >> 4;
    const int gw    = cell & (GW - 1);
    const int gh    = (cell >> 6) & (GH - 1);
    const int b     = cell >> 12;

    // ---- Bulk loads first: 4x LDG.128 per thread (2 rows x 64 float4) ----
    const float4* gs = (const float4*)grid_state + (size_t)r0 * (FEAT / 4);
    float4 v[4];
    #pragma unroll
    for (int j = 0; j < 4; j++)
        v[j] = gs[lane + 32 * j];

    // ---- Lanes 0/1: per-row scalars (overlap the bulk-load latency) ----
    float alpha_mine = 0.0f;
    if (lane < 2) {
        const int row = r0 + lane;
        const int o   = row & (NOBJ - 1);
        const int bo  = b * NOBJ + o;
        const float px = positions[bo * 2 + 0];
        const float py = positions[bo * 2 + 1];
        const int gwt = (int)fminf(fmaxf(px * (float)(GW - 1), 0.0f), 63.0f);
        const int ght = (int)fminf(fmaxf(py * (float)(GH - 1), 0.0f), 63.0f);
        const bool upd = (gwt == gw) && (ght == gh);
        const bool vis = occl[bo] < 0.5f;

        alpha_mine = upd ? (vis ? 0.8f : 0.3f) : 0.0f;

        float c  = grid_conf[row];
        float tm = grid_temp[row];
        if (upd) {
            c  = vis ? fminf(1.0f, c * 0.9f + 0.5f) : c * DECAY;
            tm += vis ? 1.0f : 0.5f;
        }
        // trailing pair at float offset row*258 + 256 (even -> 8B aligned)
        *(float2*)(out + (size_t)row * ROW_OUT + FEAT) = make_float2(c * DECAY, tm);
    }
    const float a0 = __shfl_sync(0xffffffffu, alpha_mine, 0);
    const float a1 = __shfl_sync(0xffffffffu, alpha_mine, 1);

    // ---- Blend + store: row known at compile time per j ----
    #pragma unroll
    for (int j = 0; j < 4; j++) {
        const int rl  = (j >> 1);                // 0 for j=0,1 ; 1 for j=2,3
        const int q   = lane + 32 * (j & 1);     // float4 index within row
        const int row = r0 + rl;
        const float a = rl ? a1 : a0;
        if (a != 0.0f) {                         // warp-uniform, ~never taken
            const int bo = b * NOBJ + (row & (NOBJ - 1));
            const float4 o4 = ((const float4*)(obj_feat + (size_t)bo * FEAT))[q];
            const float ia = 1.0f - a;
            v[j].x = a * o4.x + ia * v[j].x;
            v[j].y = a * o4.y + ia * v[j].y;
            v[j].z = a * o4.z + ia * v[j].z;
            v[j].w = a * o4.w + ia * v[j].w;
        }
        float* orow = out + (size_t)row * ROW_OUT + 4 * q;  // 8B aligned
        *(float2*)(orow)     = make_float2(v[j].x, v[j].y);
        *(float2*)(orow + 2) = make_float2(v[j].z, v[j].w);
    }
}

extern "C" void kernel_launch(void* const* d_in, const int* in_sizes, int n_in,
                              void* d_out, int out_size)
{
    const float* grid_state = (const float*)d_in[0];
    const float* grid_conf  = (const float*)d_in[1];
    const float* grid_temp  = (const float*)d_in[2];
    const float* obj_feat   = (const float*)d_in[3];
    const float* positions  = (const float*)d_in[4];
    const float* occl       = (const float*)d_in[5];
    float* out = (float*)d_out;

    smg_kernel<<<NROWS / 16, 256>>>(grid_state, grid_conf, grid_temp,
                                    obj_feat, positions, occl, out);
}